// round 3
// baseline (speedup 1.0000x reference)
#include <cuda_runtime.h>
#include <math.h>

// Problem constants
#define B 64
#define T 128
#define I 1024
#define H 4096
#define NNZ_IH 262144
#define NNZ_HH 1048576
#define LN_EPS 1e-5f

// Persistent-kernel geometry
#define CB 8                 // batch columns per chunk
#define NG 8                 // number of chunks (B/CB)
#define GCTAS 18             // CTAs per chunk group
#define GRID (NG * GCTAS)    // 144 <= 148 SMs, 1 CTA/SM -> co-resident
#define THREADS 512
#define NWARP 16
#define RPC 228              // ceil(H / GCTAS)
#define MAXRW 15             // ceil(RPC / NWARP)
#define SMEM_RNN ((CB * I + CB * H) * 4)   // 160 KB

// ---------------- device scratch (static, no allocations) ----------------
__device__ __align__(16) float g_xT[(size_t)T * NG * CB * I];  // ((t*NG+g)*CB+b)*I + i
__device__ __align__(16) int2  g_ihcv[NNZ_IH];                 // (col, val-bits)
__device__ __align__(16) int2  g_hhcv[NNZ_HH];
__device__ int   g_ih_ptr[H + 1];
__device__ int   g_hh_ptr[H + 1];
__device__ int   g_ih_ofs[H];
__device__ int   g_hh_ofs[H];
__device__ __align__(16) float g_hbuf[(size_t)B * H];          // bglob*H + r
__device__ float g_stats[(size_t)T * B * 2];                   // (sum, sumsq); kept zeroed
__device__ unsigned g_bcnt[NG];
__device__ unsigned g_bgen[NG];

// ---------------- preprocessing ----------------

__global__ void k_init() {
    int idx = blockIdx.x * blockDim.x + threadIdx.x;
    int stride = gridDim.x * blockDim.x;
    for (int j = idx; j < H; j += stride) { g_ih_ofs[j] = 0; g_hh_ofs[j] = 0; }
}

__global__ void k_hist(const int* __restrict__ ih_rows, const int* __restrict__ hh_rows) {
    int idx = blockIdx.x * blockDim.x + threadIdx.x;
    int stride = gridDim.x * blockDim.x;
    for (int e = idx; e < NNZ_HH; e += stride) {
        atomicAdd(&g_hh_ofs[hh_rows[e]], 1);
        if (e < NNZ_IH) atomicAdd(&g_ih_ofs[ih_rows[e]], 1);
    }
}

// single block, 1024 threads: exclusive scan of both 4096-entry histograms
__global__ void k_scan() {
    __shared__ int s[H];
    __shared__ int aux[1024];
    int tid = threadIdx.x;
    for (int pass = 0; pass < 2; pass++) {
        int* cnt = pass ? g_hh_ofs : g_ih_ofs;
        int* ptr = pass ? g_hh_ptr : g_ih_ptr;
        for (int j = tid; j < H; j += 1024) s[j] = cnt[j];
        __syncthreads();
        int base = tid * 4;
        int a0 = s[base], a1 = s[base + 1], a2 = s[base + 2], a3 = s[base + 3];
        int tsum = a0 + a1 + a2 + a3;
        aux[tid] = tsum;
        __syncthreads();
        for (int off = 1; off < 1024; off <<= 1) {
            int v = (tid >= off) ? aux[tid - off] : 0;
            __syncthreads();
            aux[tid] += v;
            __syncthreads();
        }
        int excl = aux[tid] - tsum;
        int p0 = excl, p1 = excl + a0, p2 = excl + a0 + a1, p3 = excl + a0 + a1 + a2;
        ptr[base] = p0; ptr[base + 1] = p1; ptr[base + 2] = p2; ptr[base + 3] = p3;
        cnt[base] = p0; cnt[base + 1] = p1; cnt[base + 2] = p2; cnt[base + 3] = p3;
        if (tid == 1023) ptr[H] = aux[1023];
        __syncthreads();
    }
}

__global__ void k_scatter(const int* __restrict__ ih_rows, const int* __restrict__ ih_cols,
                          const float* __restrict__ ih_vals,
                          const int* __restrict__ hh_rows, const int* __restrict__ hh_cols,
                          const float* __restrict__ hh_vals) {
    int idx = blockIdx.x * blockDim.x + threadIdx.x;
    int stride = gridDim.x * blockDim.x;
    for (int e = idx; e < NNZ_HH; e += stride) {
        int r = hh_rows[e];
        int p = atomicAdd(&g_hh_ofs[r], 1);
        g_hhcv[p] = make_int2(hh_cols[e], __float_as_int(hh_vals[e]));
        if (e < NNZ_IH) {
            int r2 = ih_rows[e];
            int p2 = atomicAdd(&g_ih_ofs[r2], 1);
            g_ihcv[p2] = make_int2(ih_cols[e], __float_as_int(ih_vals[e]));
        }
    }
}

// x (B, T, I) -> g_xT[((t*NG+g)*CB+b')*I + i]; contiguous i on both sides
__global__ void k_transpose(const float* __restrict__ x) {
    size_t idx = (size_t)blockIdx.x * blockDim.x + threadIdx.x;
    size_t stride = (size_t)gridDim.x * blockDim.x;
    const size_t total = (size_t)T * NG * CB * I;
    for (size_t j = idx; j < total; j += stride) {
        int i  = (int)(j % I);
        size_t rest = j / I;
        int bp = (int)(rest % CB);
        size_t rest2 = rest / CB;
        int g  = (int)(rest2 % NG);
        int t  = (int)(rest2 / NG);
        int bg = g * CB + bp;
        g_xT[j] = x[((size_t)bg * T + t) * I + i];
    }
}

// ---------------- per-group barrier (sense via monotonic generation) ----------------

__device__ __forceinline__ void group_barrier(int g) {
    __syncthreads();
    if (threadIdx.x == 0) {
        __threadfence();
        unsigned gen = atomicAdd(&g_bgen[g], 0u);
        unsigned arr = atomicAdd(&g_bcnt[g], 1u);
        if (arr == GCTAS - 1) {
            atomicExch(&g_bcnt[g], 0u);
            __threadfence();
            atomicAdd(&g_bgen[g], 1u);
        } else {
            while (atomicAdd(&g_bgen[g], 0u) == gen) { __nanosleep(128); }
        }
        __threadfence();
    }
    __syncthreads();
}

// ---------------- persistent fused RNN kernel ----------------

__global__ void __launch_bounds__(THREADS, 1)
k_rnn(const float* __restrict__ b_ih, const float* __restrict__ b_hh,
      const float* __restrict__ gamma, const float* __restrict__ beta,
      float* __restrict__ out) {
    extern __shared__ float sm[];
    float* xs = sm;             // [CB][I]  b-major
    float* hs = sm + CB * I;    // [CB][H]  b-major
    __shared__ float s_sum[CB], s_sq[CB];

    const int cta = blockIdx.x;
    const int g   = cta / GCTAS;
    const int sub = cta % GCTAS;
    const int r0  = sub * RPC;
    const int r1  = min(H, r0 + RPC);
    const int tid = threadIdx.x;
    const int w   = tid >> 5;
    const int lane = tid & 31;
    const int q   = lane >> 3;     // nnz sub-stream 0..3
    const int bb  = lane & 7;      // local batch column 0..7
    const int bglob = g * CB + bb;

    const float* xrow = xs + bb * I;
    const float* hrow = hs + bb * H;

    for (int t = 0; t < T; t++) {
        // ---- phase A: stage x_t and h chunks into smem ----
        {
            const float4* xsrc = reinterpret_cast<const float4*>(
                g_xT + (size_t)((t * NG + g) * CB) * I);
            float4* xd = reinterpret_cast<float4*>(xs);
            for (int j = tid; j < CB * I / 4; j += THREADS) xd[j] = xsrc[j];
            if (t > 0) {
                const float4* hsrc = reinterpret_cast<const float4*>(
                    g_hbuf + (size_t)g * CB * H);
                float4* hd = reinterpret_cast<float4*>(hs);
                for (int j = tid; j < CB * H / 4; j += THREADS) hd[j] = __ldcg(hsrc + j);
            }
            if (tid < CB) { s_sum[tid] = 0.f; s_sq[tid] = 0.f; }
        }
        __syncthreads();

        // ---- phase B: spmm (ih + hh) + tanh, act kept in registers ----
        float actreg[MAXRW];
        float lsum = 0.f, lsq = 0.f;
        #pragma unroll
        for (int i = 0; i < MAXRW; i++) {
            int r = r0 + w + (i << 4);
            float a = 0.f;
            if (r < r1) {                              // warp-uniform predicate
                float acc0 = 0.f, acc1 = 0.f;
                int s = __ldg(&g_ih_ptr[r]), e = __ldg(&g_ih_ptr[r + 1]);
                int k = s + q;
                for (; k + 4 < e; k += 8) {
                    int2 cv0 = g_ihcv[k];
                    int2 cv1 = g_ihcv[k + 4];
                    acc0 += __int_as_float(cv0.y) * xrow[cv0.x];
                    acc1 += __int_as_float(cv1.y) * xrow[cv1.x];
                }
                if (k < e) {
                    int2 cv = g_ihcv[k];
                    acc0 += __int_as_float(cv.y) * xrow[cv.x];
                }
                if (t > 0) {
                    s = __ldg(&g_hh_ptr[r]); e = __ldg(&g_hh_ptr[r + 1]);
                    k = s + q;
                    for (; k + 4 < e; k += 8) {
                        int2 cv0 = g_hhcv[k];
                        int2 cv1 = g_hhcv[k + 4];
                        acc0 += __int_as_float(cv0.y) * hrow[cv0.x];
                        acc1 += __int_as_float(cv1.y) * hrow[cv1.x];
                    }
                    if (k < e) {
                        int2 cv = g_hhcv[k];
                        acc0 += __int_as_float(cv.y) * hrow[cv.x];
                    }
                }
                float acc = acc0 + acc1;
                acc += __shfl_xor_sync(0xffffffffu, acc, 8);   // reduce over q
                acc += __shfl_xor_sync(0xffffffffu, acc, 16);
                a = tanhf(acc + __ldg(&b_ih[r]) + __ldg(&b_hh[r]));
                lsum += a; lsq += a * a;
            }
            actreg[i] = a;
        }

        // ---- LN stats: smem reduce, then one global atomic per (b) per CTA ----
        if (q == 0) { atomicAdd(&s_sum[bb], lsum); atomicAdd(&s_sq[bb], lsq); }
        __syncthreads();
        if (tid < CB) {
            atomicAdd(&g_stats[((size_t)t * B + g * CB + tid) * 2 + 0], s_sum[tid]);
            atomicAdd(&g_stats[((size_t)t * B + g * CB + tid) * 2 + 1], s_sq[tid]);
        }
        group_barrier(g);   // alpha: all group stats visible

        // ---- phase C: finalize LN, write h and out ----
        float ssum = __ldcg(&g_stats[((size_t)t * B + bglob) * 2 + 0]);
        float ssq  = __ldcg(&g_stats[((size_t)t * B + bglob) * 2 + 1]);
        float mu  = ssum * (1.0f / (float)H);
        float inv = rsqrtf(ssq * (1.0f / (float)H) - mu * mu + LN_EPS);
        #pragma unroll
        for (int i = 0; i < MAXRW; i++) {
            int r = r0 + w + (i << 4);
            if (r < r1 && q == 0) {
                float hv = (actreg[i] - mu) * inv * __ldg(&gamma[r]) + __ldg(&beta[r]);
                __stcg(&g_hbuf[(size_t)bglob * H + r], hv);
                out[((size_t)bglob * T + t) * H + r] = hv;
                if (t == T - 1)
                    out[(size_t)B * T * H + (size_t)bglob * H + r] = hv;
            }
        }
        group_barrier(g);   // beta: h writes visible before next step's staging

        // replay-safe stats reset (slot t reused only on next graph replay)
        if (sub == 0 && tid < 2 * CB) {
            g_stats[((size_t)t * B + g * CB) * 2 + tid] = 0.f;
        }
    }
}

// ---------------- launch ----------------

extern "C" void kernel_launch(void* const* d_in, const int* in_sizes, int n_in,
                              void* d_out, int out_size) {
    const float* x       = (const float*)d_in[0];
    const int*   ih_rows = (const int*)  d_in[1];
    const int*   ih_cols = (const int*)  d_in[2];
    const float* ih_vals = (const float*)d_in[3];
    const int*   hh_rows = (const int*)  d_in[4];
    const int*   hh_cols = (const int*)  d_in[5];
    const float* hh_vals = (const float*)d_in[6];
    const float* b_ih    = (const float*)d_in[7];
    const float* b_hh    = (const float*)d_in[8];
    const float* gamma   = (const float*)d_in[9];
    const float* beta    = (const float*)d_in[10];
    float* out = (float*)d_out;

    cudaFuncSetAttribute(k_rnn, cudaFuncAttributeMaxDynamicSharedMemorySize, SMEM_RNN);

    // preprocessing: COO -> CSR (counting sort) + x transpose
    k_init<<<512, 256>>>();
    k_hist<<<1024, 256>>>(ih_rows, hh_rows);
    k_scan<<<1, 1024>>>();
    k_scatter<<<1024, 256>>>(ih_rows, ih_cols, ih_vals, hh_rows, hh_cols, hh_vals);
    k_transpose<<<4096, 256>>>(x);

    // whole recurrence in one persistent kernel
    k_rnn<<<GRID, THREADS, SMEM_RNN>>>(b_ih, b_hh, gamma, beta, out);
}

// round 4
// speedup vs baseline: 1.3468x; 1.3468x over previous
#include <cuda_runtime.h>
#include <cuda_fp16.h>
#include <math.h>

// Problem constants
#define B 64
#define T 128
#define I 1024
#define H 4096
#define NNZ_IH 262144
#define NNZ_HH 1048576
#define LN_EPS 1e-5f

// Geometry
#define NCLS 4               // column classes (c & 3) -> bank-octet partitioning
#define CB 16                // batch columns per group
#define NG 4                 // groups (B / CB)
#define GCTAS 36             // CTAs per group
#define GRID (NG * GCTAS)    // 144 <= 148 SMs, 1 CTA/SM
#define THREADS 512
#define RPC 114              // ceil(H / GCTAS)
#define CAP_IH (NNZ_IH + H * NCLS)
#define CAP_HH (NNZ_HH + H * NCLS)
#define SMEM_RNN ((I + H) * CB * 2)   // fp16: 160 KB

// ---------------- device scratch ----------------
__device__ __align__(16) __half g_xh[(size_t)T * NG * I * CB];   // 16.8 MB
__device__ __align__(16) int2   g_ihcv[CAP_IH];
__device__ __align__(16) int2   g_hhcv[CAP_HH];
__device__ int g_p4_ih[H * NCLS];
__device__ int g_cnt4_ih[H * NCLS];
__device__ int g_ofs4_ih[H * NCLS];
__device__ int g_p4_hh[H * NCLS];
__device__ int g_cnt4_hh[H * NCLS];
__device__ int g_ofs4_hh[H * NCLS];
__device__ __align__(16) __half g_act16[2][(size_t)NG * H * CB]; // 1 MB
__device__ __align__(16) float  g_actf32[2][(size_t)NG * H * CB];// 2 MB
__device__ unsigned g_bcnt[NG];
__device__ unsigned g_bgen[NG];

// ---------------- preprocessing ----------------

__global__ void k_init() {
    int idx = blockIdx.x * blockDim.x + threadIdx.x;
    int stride = gridDim.x * blockDim.x;
    for (int j = idx; j < H * NCLS; j += stride) { g_cnt4_ih[j] = 0; g_cnt4_hh[j] = 0; }
}

__global__ void k_zero() {
    size_t idx = (size_t)blockIdx.x * blockDim.x + threadIdx.x;
    size_t stride = (size_t)gridDim.x * blockDim.x;
    int2 z = make_int2(0, 0);
    for (size_t j = idx; j < CAP_IH; j += stride) g_ihcv[j] = z;
    for (size_t j = idx; j < CAP_HH; j += stride) g_hhcv[j] = z;
}

__global__ void k_hist(const int* __restrict__ ih_rows, const int* __restrict__ ih_cols,
                       const int* __restrict__ hh_rows, const int* __restrict__ hh_cols) {
    int idx = blockIdx.x * blockDim.x + threadIdx.x;
    int stride = gridDim.x * blockDim.x;
    for (int e = idx; e < NNZ_HH; e += stride) {
        atomicAdd(&g_cnt4_hh[hh_rows[e] * NCLS + (hh_cols[e] & 3)], 1);
        if (e < NNZ_IH)
            atomicAdd(&g_cnt4_ih[ih_rows[e] * NCLS + (ih_cols[e] & 3)], 1);
    }
}

// 1 block, 1024 threads: exclusive scan of padded (even) bucket sizes, both matrices
__global__ void k_scan() {
    __shared__ int aux[1024];
    int tid = threadIdx.x;
    for (int pass = 0; pass < 2; pass++) {
        const int* cnt = pass ? g_cnt4_hh : g_cnt4_ih;
        int* start = pass ? g_p4_hh : g_p4_ih;
        int* ofs   = pass ? g_ofs4_hh : g_ofs4_ih;
        int local[16]; int sum = 0;
        #pragma unroll
        for (int j = 0; j < 16; j++) {
            local[j] = sum;
            int c = cnt[tid * 16 + j];
            sum += (c + 1) & ~1;       // pad each bucket to even (int4 granularity)
        }
        aux[tid] = sum;
        __syncthreads();
        for (int off = 1; off < 1024; off <<= 1) {
            int v = (tid >= off) ? aux[tid - off] : 0;
            __syncthreads();
            aux[tid] += v;
            __syncthreads();
        }
        int excl = aux[tid] - sum;
        #pragma unroll
        for (int j = 0; j < 16; j++) {
            int st = excl + local[j];
            start[tid * 16 + j] = st;
            ofs[tid * 16 + j] = st;
        }
        __syncthreads();
    }
}

__global__ void k_scatter(const int* __restrict__ ih_rows, const int* __restrict__ ih_cols,
                          const float* __restrict__ ih_vals,
                          const int* __restrict__ hh_rows, const int* __restrict__ hh_cols,
                          const float* __restrict__ hh_vals) {
    int idx = blockIdx.x * blockDim.x + threadIdx.x;
    int stride = gridDim.x * blockDim.x;
    for (int e = idx; e < NNZ_HH; e += stride) {
        int r = hh_rows[e], c = hh_cols[e];
        int p = atomicAdd(&g_ofs4_hh[r * NCLS + (c & 3)], 1);
        g_hhcv[p] = make_int2(c, __float_as_int(hh_vals[e]));
        if (e < NNZ_IH) {
            int r2 = ih_rows[e], c2 = ih_cols[e];
            int p2 = atomicAdd(&g_ofs4_ih[r2 * NCLS + (c2 & 3)], 1);
            g_ihcv[p2] = make_int2(c2, __float_as_int(ih_vals[e]));
        }
    }
}

// x (B, T, I) fp32 -> g_xh[((t*NG+g)*I + i)*CB + b] fp16
__global__ void k_transpose(const float* __restrict__ x) {
    size_t idx = (size_t)blockIdx.x * blockDim.x + threadIdx.x;
    size_t stride = (size_t)gridDim.x * blockDim.x;
    const size_t total = (size_t)T * NG * I * CB;
    for (size_t j = idx; j < total; j += stride) {
        int b = (int)(j & (CB - 1));
        size_t rest = j >> 4;
        int i = (int)(rest % I);
        size_t rest2 = rest / I;
        int g = (int)(rest2 % NG);
        int t = (int)(rest2 / NG);
        int bg = g * CB + b;
        g_xh[j] = __float2half(x[((size_t)bg * T + t) * I + i]);
    }
}

// ---------------- per-group barrier (monotonic generation) ----------------

__device__ __forceinline__ void group_barrier(int g) {
    __syncthreads();
    if (threadIdx.x == 0) {
        __threadfence();
        unsigned gen = atomicAdd(&g_bgen[g], 0u);
        unsigned arr = atomicAdd(&g_bcnt[g], 1u);
        if (arr == GCTAS - 1) {
            atomicExch(&g_bcnt[g], 0u);
            __threadfence();
            atomicAdd(&g_bgen[g], 1u);
        } else {
            while (atomicAdd(&g_bgen[g], 0u) == gen) { __nanosleep(64); }
        }
        __threadfence();
    }
    __syncthreads();
}

// ---------------- fused persistent RNN ----------------

__device__ __forceinline__ void gather_pass(const int2* __restrict__ cvb,
                                            const int* __restrict__ p4,
                                            const int* __restrict__ cnt4,
                                            const __half* __restrict__ src,
                                            int r, int q, int bp, float2& acc) {
    int base = r * NCLS + q;
    int s = __ldg(&p4[base]);
    int cnt = __ldg(&cnt4[base]);
    int mx = cnt;
    mx = max(mx, __shfl_xor_sync(0xffffffffu, mx, 8));
    mx = max(mx, __shfl_xor_sync(0xffffffffu, mx, 16));
    int e = s + cnt;
    const int4* cv = reinterpret_cast<const int4*>(cvb);
    for (int j = 0; j < mx; j += 2) {
        int k = s + j;
        if (k < e) {                    // pads are zero-filled -> safe
            int4 wv = __ldg(&cv[k >> 1]);
            float2 h0 = __half22float2(*reinterpret_cast<const __half2*>(&src[wv.x * CB + 2 * bp]));
            float v0 = __int_as_float(wv.y);
            acc.x = fmaf(v0, h0.x, acc.x);
            acc.y = fmaf(v0, h0.y, acc.y);
            float2 h1 = __half22float2(*reinterpret_cast<const __half2*>(&src[wv.z * CB + 2 * bp]));
            float v1 = __int_as_float(wv.w);
            acc.x = fmaf(v1, h1.x, acc.x);
            acc.y = fmaf(v1, h1.y, acc.y);
        }
    }
}

__global__ void __launch_bounds__(THREADS, 1)
k_rnn(const float* __restrict__ b_ih, const float* __restrict__ b_hh,
      const float* __restrict__ gamma, const float* __restrict__ beta,
      float* __restrict__ out, int write_hlast) {
    extern __shared__ __half smh[];
    __half* xs = smh;            // [I][CB]
    __half* hs = smh + I * CB;   // [H][CB]
    __shared__ float s_sum[CB], s_sq[CB], s_mu[CB], s_inv[CB];

    const int cta = blockIdx.x;
    const int g   = cta / GCTAS;
    const int sub = cta % GCTAS;
    const int r0  = sub * RPC;
    const int r1  = min(H, r0 + RPC);
    const int nr  = r1 - r0;
    const int tid = threadIdx.x;
    const int w    = tid >> 5;
    const int lane = tid & 31;
    const int q    = lane >> 3;    // column class 0..3
    const int bp   = lane & 7;     // batch pair 0..7 (covers 2 b via half2)
    const int sl   = tid >> 3;     // 64 slices for stats/normalize
    const int bpp  = tid & 7;

    for (int t = 0; t <= T; t++) {
        const int pr = (t - 1) & 1;
        const int pw = t & 1;

        // ---- stage ----
        if (t > 0) {
            const float4* src = reinterpret_cast<const float4*>(
                g_act16[pr] + (size_t)g * H * CB);
            float4* dst = reinterpret_cast<float4*>(hs);
            #pragma unroll 4
            for (int j = tid; j < H * CB / 8; j += THREADS) dst[j] = __ldcg(src + j);
        }
        if (t < T) {
            const float4* src = reinterpret_cast<const float4*>(
                g_xh + ((size_t)t * NG + g) * I * CB);
            float4* dst = reinterpret_cast<float4*>(xs);
            #pragma unroll 2
            for (int j = tid; j < I * CB / 8; j += THREADS) dst[j] = src[j];
        }
        if (tid < CB) { s_sum[tid] = 0.f; s_sq[tid] = 0.f; }
        __syncthreads();

        if (t > 0) {
            // ---- local LN stats over staged act (full H, 16 b) ----
            float2 asum = make_float2(0.f, 0.f), asq = make_float2(0.f, 0.f);
            for (int j = 0; j < H / 64; j++) {
                int c = j * 64 + sl;
                float2 v = __half22float2(*reinterpret_cast<const __half2*>(&hs[c * CB + 2 * bpp]));
                asum.x += v.x; asum.y += v.y;
                asq.x += v.x * v.x; asq.y += v.y * v.y;
            }
            #pragma unroll
            for (int off = 8; off <= 16; off <<= 1) {
                asum.x += __shfl_xor_sync(0xffffffffu, asum.x, off);
                asum.y += __shfl_xor_sync(0xffffffffu, asum.y, off);
                asq.x  += __shfl_xor_sync(0xffffffffu, asq.x, off);
                asq.y  += __shfl_xor_sync(0xffffffffu, asq.y, off);
            }
            if (lane < 8) {
                atomicAdd(&s_sum[2 * bpp], asum.x);
                atomicAdd(&s_sum[2 * bpp + 1], asum.y);
                atomicAdd(&s_sq[2 * bpp], asq.x);
                atomicAdd(&s_sq[2 * bpp + 1], asq.y);
            }
            __syncthreads();
            if (tid < CB) {
                float mu = s_sum[tid] * (1.0f / (float)H);
                float var = s_sq[tid] * (1.0f / (float)H) - mu * mu;
                s_mu[tid] = mu;
                s_inv[tid] = rsqrtf(var + LN_EPS);
            }
            __syncthreads();

            // ---- normalize staged act in place (becomes h for the gather) ----
            if (t < T) {
                float2 mu2 = make_float2(s_mu[2 * bpp], s_mu[2 * bpp + 1]);
                float2 in2 = make_float2(s_inv[2 * bpp], s_inv[2 * bpp + 1]);
                for (int j = 0; j < H / 64; j++) {
                    int c = j * 64 + sl;
                    __half2* p = reinterpret_cast<__half2*>(&hs[c * CB + 2 * bpp]);
                    float2 v = __half22float2(*p);
                    float ga = __ldg(&gamma[c]), be = __ldg(&beta[c]);
                    v.x = (v.x - mu2.x) * in2.x * ga + be;
                    v.y = (v.y - mu2.y) * in2.y * ga + be;
                    *p = __floats2half2_rn(v.x, v.y);
                }
            }

            // ---- out(t-1) from fp32 side channel (own rows only) ----
            const float* af = g_actf32[pr] + (size_t)g * H * CB;
            for (int idx = tid; idx < CB * nr; idx += THREADS) {
                int bb = idx / nr, rl = idx - bb * nr;
                int r = r0 + rl;
                float a = __ldcg(&af[(size_t)r * CB + bb]);
                float hv = (a - s_mu[bb]) * s_inv[bb] * __ldg(&gamma[r]) + __ldg(&beta[r]);
                int bglob = g * CB + bb;
                out[((size_t)bglob * T + (t - 1)) * H + r] = hv;
                if (t == T && write_hlast)
                    out[(size_t)B * T * H + (size_t)bglob * H + r] = hv;
            }
            __syncthreads();   // normalize complete before gather reads hs
        }

        // ---- gather spmm + tanh, write act (double-buffered) ----
        if (t < T) {
            __half* a16 = g_act16[pw] + (size_t)g * H * CB;
            float*  a32 = g_actf32[pw] + (size_t)g * H * CB;
            for (int r = r0 + w; r < r1; r += 16) {
                float2 acc = make_float2(0.f, 0.f);
                gather_pass(g_ihcv, g_p4_ih, g_cnt4_ih, xs, r, q, bp, acc);
                if (t > 0)
                    gather_pass(g_hhcv, g_p4_hh, g_cnt4_hh, hs, r, q, bp, acc);
                #pragma unroll
                for (int off = 8; off <= 16; off <<= 1) {
                    acc.x += __shfl_xor_sync(0xffffffffu, acc.x, off);
                    acc.y += __shfl_xor_sync(0xffffffffu, acc.y, off);
                }
                if (lane < 8) {
                    float bias = __ldg(&b_ih[r]) + __ldg(&b_hh[r]);
                    float a0 = tanhf(acc.x + bias);
                    float a1 = tanhf(acc.y + bias);
                    __half2 h2 = __floats2half2_rn(a0, a1);
                    __stcg(reinterpret_cast<unsigned int*>(&a16[(size_t)r * CB + 2 * bp]),
                           *reinterpret_cast<unsigned int*>(&h2));
                    __stcg(reinterpret_cast<float2*>(&a32[(size_t)r * CB + 2 * bp]),
                           make_float2(a0, a1));
                }
            }
        }
        group_barrier(g);
    }
}

// ---------------- launch ----------------

extern "C" void kernel_launch(void* const* d_in, const int* in_sizes, int n_in,
                              void* d_out, int out_size) {
    const float* x       = (const float*)d_in[0];
    const int*   ih_rows = (const int*)  d_in[1];
    const int*   ih_cols = (const int*)  d_in[2];
    const float* ih_vals = (const float*)d_in[3];
    const int*   hh_rows = (const int*)  d_in[4];
    const int*   hh_cols = (const int*)  d_in[5];
    const float* hh_vals = (const float*)d_in[6];
    const float* b_ih    = (const float*)d_in[7];
    const float* b_hh    = (const float*)d_in[8];
    const float* gamma   = (const float*)d_in[9];
    const float* beta    = (const float*)d_in[10];
    float* out = (float*)d_out;

    cudaFuncSetAttribute(k_rnn, cudaFuncAttributeMaxDynamicSharedMemorySize, SMEM_RNN);

    k_init<<<64, 256>>>();
    k_zero<<<1024, 256>>>();
    k_hist<<<1024, 256>>>(ih_rows, ih_cols, hh_rows, hh_cols);
    k_scan<<<1, 1024>>>();
    k_scatter<<<1024, 256>>>(ih_rows, ih_cols, ih_vals, hh_rows, hh_cols, hh_vals);
    k_transpose<<<4096, 256>>>(x);

    int write_hlast = ((size_t)out_size >= (size_t)B * T * H + (size_t)B * H) ? 1 : 0;
    k_rnn<<<GRID, THREADS, SMEM_RNN>>>(b_ih, b_hh, gamma, beta, out, write_hlast);
}

// round 6
// speedup vs baseline: 2.7164x; 2.0170x over previous
#include <cuda_runtime.h>
#include <cuda_fp16.h>
#include <math.h>

// Problem constants
#define B 64
#define T 128
#define I 1024
#define H 4096
#define NNZ_IH 262144
#define NNZ_HH 1048576
#define LN_EPS 1e-5f

// ---------------- device scratch (static, no allocations) ----------------
__device__ __align__(16) __half g_xh[(size_t)T * I * B];   // 16.8 MB, (t, i, b)
__device__ __align__(16) int2   g_ihcv[NNZ_IH];            // packed (col, val-bits)
__device__ __align__(16) int2   g_hhcv[NNZ_HH];
__device__ int   g_ih_ptr[H + 1];
__device__ int   g_hh_ptr[H + 1];
__device__ int   g_ih_ofs[H];
__device__ int   g_hh_ofs[H];
__device__ __align__(16) __half g_h16[H * B];   // (r, b) fp16 hidden for gather
__device__ __align__(16) float  g_act[H * B];   // tanh(pre), (r, b) fp32

// ---------------- preprocessing ----------------

__global__ void k_init() {
    int idx = blockIdx.x * blockDim.x + threadIdx.x;
    int stride = gridDim.x * blockDim.x;
    for (int j = idx; j < H; j += stride) { g_ih_ofs[j] = 0; g_hh_ofs[j] = 0; }
}

__global__ void k_hist(const int* __restrict__ ih_rows, const int* __restrict__ hh_rows) {
    int idx = blockIdx.x * blockDim.x + threadIdx.x;
    int stride = gridDim.x * blockDim.x;
    for (int e = idx; e < NNZ_HH; e += stride) {
        atomicAdd(&g_hh_ofs[hh_rows[e]], 1);
        if (e < NNZ_IH) atomicAdd(&g_ih_ofs[ih_rows[e]], 1);
    }
}

// single block, 1024 threads: exclusive scan of both 4096-entry histograms
__global__ void k_scan() {
    __shared__ int s[H];
    __shared__ int aux[1024];
    int tid = threadIdx.x;
    for (int pass = 0; pass < 2; pass++) {
        int* cnt = pass ? g_hh_ofs : g_ih_ofs;
        int* ptr = pass ? g_hh_ptr : g_ih_ptr;
        for (int j = tid; j < H; j += 1024) s[j] = cnt[j];
        __syncthreads();
        int base = tid * 4;
        int a0 = s[base], a1 = s[base + 1], a2 = s[base + 2], a3 = s[base + 3];
        int tsum = a0 + a1 + a2 + a3;
        aux[tid] = tsum;
        __syncthreads();
        for (int off = 1; off < 1024; off <<= 1) {
            int v = (tid >= off) ? aux[tid - off] : 0;
            __syncthreads();
            aux[tid] += v;
            __syncthreads();
        }
        int excl = aux[tid] - tsum;
        int p0 = excl, p1 = excl + a0, p2 = excl + a0 + a1, p3 = excl + a0 + a1 + a2;
        ptr[base] = p0; ptr[base + 1] = p1; ptr[base + 2] = p2; ptr[base + 3] = p3;
        cnt[base] = p0; cnt[base + 1] = p1; cnt[base + 2] = p2; cnt[base + 3] = p3;
        if (tid == 1023) ptr[H] = aux[1023];
        __syncthreads();
    }
}

__global__ void k_scatter(const int* __restrict__ ih_rows, const int* __restrict__ ih_cols,
                          const float* __restrict__ ih_vals,
                          const int* __restrict__ hh_rows, const int* __restrict__ hh_cols,
                          const float* __restrict__ hh_vals) {
    int idx = blockIdx.x * blockDim.x + threadIdx.x;
    int stride = gridDim.x * blockDim.x;
    for (int e = idx; e < NNZ_HH; e += stride) {
        int r = hh_rows[e];
        int p = atomicAdd(&g_hh_ofs[r], 1);
        g_hhcv[p] = make_int2(hh_cols[e], __float_as_int(hh_vals[e]));
        if (e < NNZ_IH) {
            int r2 = ih_rows[e];
            int p2 = atomicAdd(&g_ih_ofs[r2], 1);
            g_ihcv[p2] = make_int2(ih_cols[e], __float_as_int(ih_vals[e]));
        }
    }
}

// x (B, T, I) fp32 -> g_xh[(t*I + i)*B + b] fp16
__global__ void k_transpose(const float* __restrict__ x) {
    size_t idx = (size_t)blockIdx.x * blockDim.x + threadIdx.x;
    size_t stride = (size_t)gridDim.x * blockDim.x;
    const size_t total = (size_t)T * I * B;
    for (size_t j = idx; j < total; j += stride) {
        int b = (int)(j & (B - 1));
        int i = (int)((j >> 6) % I);
        int t = (int)((j >> 6) / I);
        g_xh[j] = __float2half(x[((size_t)b * T + t) * I + i]);
    }
}

// ---------------- per-step kernels ----------------

// warp per row; lane covers batches (2*lane, 2*lane+1) via half2 gather, fp32 accum
__global__ void __launch_bounds__(256) k_spmm(const float* __restrict__ b_ih,
                                              const float* __restrict__ b_hh, int t) {
    int row  = blockIdx.x * 8 + (threadIdx.x >> 5);
    int lane = threadIdx.x & 31;

    float bias = __ldg(&b_ih[row]) + __ldg(&b_hh[row]);
    float2 acc; acc.x = bias; acc.y = bias;

    // ---- ih pass ----
    {
        const __half2* __restrict__ xsrc =
            reinterpret_cast<const __half2*>(g_xh) + (size_t)t * I * 32;
        int s = __ldg(&g_ih_ptr[row]), e = __ldg(&g_ih_ptr[row + 1]);
        #pragma unroll 4
        for (int k = s; k < e; k++) {
            int2 cv = __ldg(&g_ihcv[k]);            // warp-broadcast, L1 stream
            float2 f = __half22float2(xsrc[cv.x * 32 + lane]);
            float v = __int_as_float(cv.y);
            acc.x = fmaf(v, f.x, acc.x);
            acc.y = fmaf(v, f.y, acc.y);
        }
    }
    // ---- hh pass (h0 == 0 -> skip at t==0) ----
    if (t > 0) {
        const __half2* __restrict__ hsrc = reinterpret_cast<const __half2*>(g_h16);
        int s = __ldg(&g_hh_ptr[row]), e = __ldg(&g_hh_ptr[row + 1]);
        #pragma unroll 4
        for (int k = s; k < e; k++) {
            int2 cv = __ldg(&g_hhcv[k]);
            float2 f = __half22float2(hsrc[cv.x * 32 + lane]);
            float v = __int_as_float(cv.y);
            acc.x = fmaf(v, f.x, acc.x);
            acc.y = fmaf(v, f.y, acc.y);
        }
    }

    float2 r2;
    r2.x = tanhf(acc.x);
    r2.y = tanhf(acc.y);
    reinterpret_cast<float2*>(g_act)[row * 32 + lane] = r2;
}

// block per batch column b: layernorm over H (fp32), write h16 + out (+h_last)
__global__ void __launch_bounds__(1024) k_ln(const float* __restrict__ gamma,
                                             const float* __restrict__ beta,
                                             float* __restrict__ out, int t,
                                             int write_hlast) {
    int b = blockIdx.x;
    int tid = threadIdx.x;

    float vals[4];
    float sum = 0.0f, sumsq = 0.0f;
    #pragma unroll
    for (int j = 0; j < 4; j++) {
        int r = tid + j * 1024;
        float a = g_act[r * B + b];
        vals[j] = a;
        sum += a;
        sumsq += a * a;
    }

    __shared__ float ssum[32], ssq[32];
    int lane = tid & 31, wid = tid >> 5;
    #pragma unroll
    for (int off = 16; off > 0; off >>= 1) {
        sum   += __shfl_xor_sync(0xffffffffu, sum, off);
        sumsq += __shfl_xor_sync(0xffffffffu, sumsq, off);
    }
    if (lane == 0) { ssum[wid] = sum; ssq[wid] = sumsq; }
    __syncthreads();
    if (wid == 0) {
        float s = ssum[lane], q = ssq[lane];
        #pragma unroll
        for (int off = 16; off > 0; off >>= 1) {
            s += __shfl_xor_sync(0xffffffffu, s, off);
            q += __shfl_xor_sync(0xffffffffu, q, off);
        }
        if (lane == 0) { ssum[0] = s; ssq[0] = q; }
    }
    __syncthreads();
    float mu  = ssum[0] * (1.0f / (float)H);
    float var = ssq[0] * (1.0f / (float)H) - mu * mu;
    float inv = rsqrtf(var + LN_EPS);

    float* outp = out + ((size_t)b * T + t) * H;
    #pragma unroll
    for (int j = 0; j < 4; j++) {
        int r = tid + j * 1024;
        float hv = (vals[j] - mu) * inv * __ldg(&gamma[r]) + __ldg(&beta[r]);
        g_h16[r * B + b] = __float2half(hv);   // fp16 copy for next-step gather
        outp[r] = hv;                          // coalesced fp32 output
        if (write_hlast)
            out[(size_t)B * T * H + (size_t)b * H + r] = hv;
    }
}

// ---------------- launch ----------------

extern "C" void kernel_launch(void* const* d_in, const int* in_sizes, int n_in,
                              void* d_out, int out_size) {
    const float* x       = (const float*)d_in[0];
    const int*   ih_rows = (const int*)  d_in[1];
    const int*   ih_cols = (const int*)  d_in[2];
    const float* ih_vals = (const float*)d_in[3];
    const int*   hh_rows = (const int*)  d_in[4];
    const int*   hh_cols = (const int*)  d_in[5];
    const float* hh_vals = (const float*)d_in[6];
    const float* b_ih    = (const float*)d_in[7];
    const float* b_hh    = (const float*)d_in[8];
    const float* gamma   = (const float*)d_in[9];
    const float* beta    = (const float*)d_in[10];
    float* out = (float*)d_out;

    // preprocessing: COO -> CSR (counting sort) + x transpose to fp16
    k_init<<<64, 256>>>();
    k_hist<<<1024, 256>>>(ih_rows, hh_rows);
    k_scan<<<1, 1024>>>();
    k_scatter<<<1024, 256>>>(ih_rows, ih_cols, ih_vals, hh_rows, hh_cols, hh_vals);
    k_transpose<<<4096, 256>>>(x);

    int can_hlast = ((size_t)out_size >= (size_t)B * T * H + (size_t)B * H) ? 1 : 0;

    // sequential recurrence
    for (int t = 0; t < T; t++) {
        k_spmm<<<512, 256>>>(b_ih, b_hh, t);
        k_ln<<<64, 1024>>>(gamma, beta, out, t, (t == T - 1) ? can_hlast : 0);
    }
}

// round 8
// speedup vs baseline: 3.0871x; 1.1365x over previous
#include <cuda_runtime.h>
#include <cuda_fp16.h>
#include <math.h>

// Problem constants
#define B 64
#define T 128
#define I 1024
#define H 4096
#define NNZ_IH 262144
#define NNZ_HH 1048576
#define LN_EPS 1e-5f

#define CAP_IH (NNZ_IH + H)   // even-padded CSR
#define CAP_HH (NNZ_HH + H)

// ---------------- device scratch (static, no allocations) ----------------
__device__ __align__(16) __half g_xh[(size_t)T * I * B];        // 16.8 MB (t,i,b) fp16
__device__ __align__(16) int2   g_ihcv[CAP_IH];                 // (col, val-bits)
__device__ __align__(16) int2   g_hhcv[CAP_HH];                 // (col, gamma-folded val)
__device__ int   g_ih_ptr[H + 1];
__device__ int   g_hh_ptr[H + 1];
__device__ int   g_ih_ofs[H];
__device__ int   g_hh_ofs[H];
__device__ float g_Sg[H];                                       // sum w_hh * gamma
__device__ float g_Sb[H];                                       // sum w_hh * beta
__device__ __align__(16) __half g_a16[(size_t)T * H * B];       // 64 MB act fp16 (t,r,b)
__device__ __align__(16) float  g_a32[(size_t)T * H * B];       // 128 MB act fp32 (t,r,b)
__device__ __align__(16) float  g_stats[(size_t)T * B * 2];     // (sum, sumsq) per (t,b)

// ---------------- preprocessing ----------------

__global__ void k_init() {
    int idx = blockIdx.x * blockDim.x + threadIdx.x;
    int stride = gridDim.x * blockDim.x;
    for (int j = idx; j < H; j += stride) {
        g_ih_ofs[j] = 0; g_hh_ofs[j] = 0; g_Sg[j] = 0.f; g_Sb[j] = 0.f;
    }
    for (int j = idx; j < T * B * 2; j += stride) g_stats[j] = 0.f;
}

__global__ void k_zero() {
    int idx = blockIdx.x * blockDim.x + threadIdx.x;
    int stride = gridDim.x * blockDim.x;
    int2 z = make_int2(0, 0);
    for (int j = idx; j < CAP_IH; j += stride) g_ihcv[j] = z;
    for (int j = idx; j < CAP_HH; j += stride) g_hhcv[j] = z;
}

__global__ void k_hist(const int* __restrict__ ih_rows, const int* __restrict__ hh_rows) {
    int idx = blockIdx.x * blockDim.x + threadIdx.x;
    int stride = gridDim.x * blockDim.x;
    for (int e = idx; e < NNZ_HH; e += stride) {
        atomicAdd(&g_hh_ofs[hh_rows[e]], 1);
        if (e < NNZ_IH) atomicAdd(&g_ih_ofs[ih_rows[e]], 1);
    }
}

// 1 block, 1024 threads: exclusive scan of even-padded row sizes, both matrices
__global__ void k_scan() {
    __shared__ int s[H];
    __shared__ int aux[1024];
    int tid = threadIdx.x;
    for (int pass = 0; pass < 2; pass++) {
        int* cnt = pass ? g_hh_ofs : g_ih_ofs;
        int* ptr = pass ? g_hh_ptr : g_ih_ptr;
        for (int j = tid; j < H; j += 1024) s[j] = (cnt[j] + 1) & ~1;  // pad even
        __syncthreads();
        int base = tid * 4;
        int a0 = s[base], a1 = s[base + 1], a2 = s[base + 2], a3 = s[base + 3];
        int tsum = a0 + a1 + a2 + a3;
        aux[tid] = tsum;
        __syncthreads();
        for (int off = 1; off < 1024; off <<= 1) {
            int v = (tid >= off) ? aux[tid - off] : 0;
            __syncthreads();
            aux[tid] += v;
            __syncthreads();
        }
        int excl = aux[tid] - tsum;
        int p0 = excl, p1 = excl + a0, p2 = excl + a0 + a1, p3 = excl + a0 + a1 + a2;
        ptr[base] = p0; ptr[base + 1] = p1; ptr[base + 2] = p2; ptr[base + 3] = p3;
        cnt[base] = p0; cnt[base + 1] = p1; cnt[base + 2] = p2; cnt[base + 3] = p3;
        if (tid == 1023) ptr[H] = aux[1023];
        __syncthreads();
    }
}

// scatter into padded CSR; fold gamma into hh vals; accumulate Sg/Sb row sums
__global__ void k_scatter(const int* __restrict__ ih_rows, const int* __restrict__ ih_cols,
                          const float* __restrict__ ih_vals,
                          const int* __restrict__ hh_rows, const int* __restrict__ hh_cols,
                          const float* __restrict__ hh_vals,
                          const float* __restrict__ gamma, const float* __restrict__ beta) {
    int idx = blockIdx.x * blockDim.x + threadIdx.x;
    int stride = gridDim.x * blockDim.x;
    for (int e = idx; e < NNZ_HH; e += stride) {
        int r = hh_rows[e], c = hh_cols[e];
        float v = hh_vals[e];
        float ga = __ldg(&gamma[c]);
        int p = atomicAdd(&g_hh_ofs[r], 1);
        g_hhcv[p] = make_int2(c, __float_as_int(v * ga));
        atomicAdd(&g_Sg[r], v * ga);
        atomicAdd(&g_Sb[r], v * __ldg(&beta[c]));
        if (e < NNZ_IH) {
            int r2 = ih_rows[e];
            int p2 = atomicAdd(&g_ih_ofs[r2], 1);
            g_ihcv[p2] = make_int2(ih_cols[e], __float_as_int(ih_vals[e]));
        }
    }
}

// x (B, T, I) fp32 -> g_xh[(t*I + i)*B + b] fp16
__global__ void k_transpose(const float* __restrict__ x) {
    size_t idx = (size_t)blockIdx.x * blockDim.x + threadIdx.x;
    size_t stride = (size_t)gridDim.x * blockDim.x;
    const size_t total = (size_t)T * I * B;
    for (size_t j = idx; j < total; j += stride) {
        int b = (int)(j & (B - 1));
        int i = (int)((j >> 6) % I);
        int t = (int)((j >> 6) / I);
        g_xh[j] = __float2half(x[((size_t)b * T + t) * I + i]);
    }
}

// ---------------- recurrence: one kernel per step ----------------
// warp per row; lane covers batches (2l, 2l+1). Gathers raw fp16 acts of t-1,
// LN applied algebraically via (mu, inv) stats + precomputed Sg/Sb.

__global__ void __launch_bounds__(256) k_spmm(const float* __restrict__ b_ih,
                                              const float* __restrict__ b_hh, int t) {
    __shared__ float s_a[8][64];
    int w    = threadIdx.x >> 5;
    int row  = blockIdx.x * 8 + w;
    int lane = threadIdx.x & 31;

    float mu0 = 0.f, iv0 = 0.f, mu1 = 0.f, iv1 = 0.f;
    if (t > 0) {
        float4 st = *reinterpret_cast<const float4*>(&g_stats[((size_t)(t - 1) * B + 2 * lane) * 2]);
        mu0 = st.x * (1.0f / (float)H);
        iv0 = rsqrtf(st.y * (1.0f / (float)H) - mu0 * mu0 + LN_EPS);
        mu1 = st.z * (1.0f / (float)H);
        iv1 = rsqrtf(st.w * (1.0f / (float)H) - mu1 * mu1 + LN_EPS);
    }

    float2 accx = make_float2(0.f, 0.f);
    // ---- ih pass: 2 nnz per int4 ----
    {
        const __half2* __restrict__ xsrc =
            reinterpret_cast<const __half2*>(g_xh) + (size_t)t * I * 32;
        const int4* cv = reinterpret_cast<const int4*>(g_ihcv);
        int s = __ldg(&g_ih_ptr[row]) >> 1, e = __ldg(&g_ih_ptr[row + 1]) >> 1;
        #pragma unroll 4
        for (int k = s; k < e; k++) {
            int4 wv = __ldg(&cv[k]);
            float2 f0 = __half22float2(xsrc[wv.x * 32 + lane]);
            float v0 = __int_as_float(wv.y);
            float2 f1 = __half22float2(xsrc[wv.z * 32 + lane]);
            float v1 = __int_as_float(wv.w);
            accx.x = fmaf(v0, f0.x, accx.x); accx.y = fmaf(v0, f0.y, accx.y);
            accx.x = fmaf(v1, f1.x, accx.x); accx.y = fmaf(v1, f1.y, accx.y);
        }
    }
    float2 acch = make_float2(0.f, 0.f);
    if (t > 0) {
        const __half2* __restrict__ hsrc =
            reinterpret_cast<const __half2*>(g_a16) + (size_t)(t - 1) * H * 32;
        const int4* cv = reinterpret_cast<const int4*>(g_hhcv);
        int s = __ldg(&g_hh_ptr[row]) >> 1, e = __ldg(&g_hh_ptr[row + 1]) >> 1;
        #pragma unroll 4
        for (int k = s; k < e; k++) {
            int4 wv = __ldg(&cv[k]);
            float2 f0 = __half22float2(hsrc[wv.x * 32 + lane]);
            float v0 = __int_as_float(wv.y);
            float2 f1 = __half22float2(hsrc[wv.z * 32 + lane]);
            float v1 = __int_as_float(wv.w);
            acch.x = fmaf(v0, f0.x, acch.x); acch.y = fmaf(v0, f0.y, acch.y);
            acch.x = fmaf(v1, f1.x, acch.x); acch.y = fmaf(v1, f1.y, acch.y);
        }
    }

    float cst = __ldg(&b_ih[row]) + __ldg(&b_hh[row]) + ((t > 0) ? __ldg(&g_Sb[row]) : 0.f);
    float sg  = (t > 0) ? __ldg(&g_Sg[row]) : 0.f;
    float pre0 = accx.x + cst + iv0 * acch.x - mu0 * iv0 * sg;
    float pre1 = accx.y + cst + iv1 * acch.y - mu1 * iv1 * sg;
    float a0 = tanhf(pre0);
    float a1 = tanhf(pre1);

    // archive acts
    __half2 h2 = __floats2half2_rn(a0, a1);
    reinterpret_cast<__half2*>(g_a16)[((size_t)t * H + row) * 32 + lane] = h2;
    reinterpret_cast<float2*>(g_a32)[((size_t)t * H + row) * 32 + lane] = make_float2(a0, a1);

    // block-tile LN stats -> global atomics (128 spread addresses)
    s_a[w][2 * lane] = a0;
    s_a[w][2 * lane + 1] = a1;
    __syncthreads();
    if (threadIdx.x < 64) {
        int b = threadIdx.x;
        float s = 0.f, q = 0.f;
        #pragma unroll
        for (int j = 0; j < 8; j++) { float v = s_a[j][b]; s += v; q += v * v; }
        atomicAdd(&g_stats[((size_t)t * B + b) * 2 + 0], s);
        atomicAdd(&g_stats[((size_t)t * B + b) * 2 + 1], q);
    }
}

// ---------------- batched output writer (off the recurrence path) ----------------
// block = (t, 256-row chunk): smem-transpose act32 tile, write out coalesced.
#define OUT_SMEM (256 * 65 * 4)

__global__ void __launch_bounds__(256) k_out(const float* __restrict__ gamma,
                                             const float* __restrict__ beta,
                                             float* __restrict__ out, int write_hlast) {
    extern __shared__ float s[];   // [256][65]
    int t = blockIdx.x >> 4;
    int r0 = (blockIdx.x & 15) * 256;
    int tid = threadIdx.x;

    const float2* a2 = reinterpret_cast<const float2*>(g_a32) + ((size_t)t * H + r0) * 32;
    for (int j = tid; j < 256 * 32; j += 256) {
        int r = j >> 5, l = j & 31;
        float2 v = __ldg(&a2[r * 32 + l]);
        s[r * 65 + 2 * l] = v.x;
        s[r * 65 + 2 * l + 1] = v.y;
    }
    __syncthreads();

    int w = tid >> 5, lane = tid & 31;
    float ga[8], be[8];
    #pragma unroll
    for (int j = 0; j < 8; j++) {
        int r = r0 + lane + 32 * j;
        ga[j] = __ldg(&gamma[r]); be[j] = __ldg(&beta[r]);
    }
    for (int bb = w; bb < 64; bb += 8) {
        float2 st = *reinterpret_cast<const float2*>(&g_stats[((size_t)t * B + bb) * 2]);
        float mu = st.x * (1.0f / (float)H);
        float iv = rsqrtf(st.y * (1.0f / (float)H) - mu * mu + LN_EPS);
        #pragma unroll
        for (int j = 0; j < 8; j++) {
            int rl = lane + 32 * j;
            float hv = (s[rl * 65 + bb] - mu) * iv * ga[j] + be[j];
            out[(size_t)bb * T * H + (size_t)t * H + r0 + rl] = hv;
            if (write_hlast && t == T - 1)
                out[(size_t)B * T * H + (size_t)bb * H + r0 + rl] = hv;
        }
    }
}

// ---------------- launch ----------------

extern "C" void kernel_launch(void* const* d_in, const int* in_sizes, int n_in,
                              void* d_out, int out_size) {
    const float* x       = (const float*)d_in[0];
    const int*   ih_rows = (const int*)  d_in[1];
    const int*   ih_cols = (const int*)  d_in[2];
    const float* ih_vals = (const float*)d_in[3];
    const int*   hh_rows = (const int*)  d_in[4];
    const int*   hh_cols = (const int*)  d_in[5];
    const float* hh_vals = (const float*)d_in[6];
    const float* b_ih    = (const float*)d_in[7];
    const float* b_hh    = (const float*)d_in[8];
    const float* gamma   = (const float*)d_in[9];
    const float* beta    = (const float*)d_in[10];
    float* out = (float*)d_out;

    cudaFuncSetAttribute(k_out, cudaFuncAttributeMaxDynamicSharedMemorySize, OUT_SMEM);

    // preprocessing
    k_init<<<128, 256>>>();
    k_zero<<<1024, 256>>>();
    k_hist<<<1024, 256>>>(ih_rows, hh_rows);
    k_scan<<<1, 1024>>>();
    k_scatter<<<1024, 256>>>(ih_rows, ih_cols, ih_vals, hh_rows, hh_cols, hh_vals,
                             gamma, beta);
    k_transpose<<<4096, 256>>>(x);

    // recurrence: only spmm kernels on the critical path
    for (int t = 0; t < T; t++)
        k_spmm<<<512, 256>>>(b_ih, b_hh, t);

    // batched LN + output writes
    int can_hlast = ((size_t)out_size >= (size_t)B * T * H + (size_t)B * H) ? 1 : 0;
    k_out<<<T * 16, 256, OUT_SMEM>>>(gamma, beta, out, can_hlast);
}

// round 9
// speedup vs baseline: 3.6022x; 1.1668x over previous
#include <cuda_runtime.h>
#include <cuda_fp16.h>
#include <math.h>

// Problem constants
#define B 64
#define T 128
#define I 1024
#define H 4096
#define NNZ_IH 262144
#define NNZ_HH 1048576
#define LN_EPS 1e-5f

// ---------------- device scratch (static, no allocations) ----------------
__device__ __align__(16) __half g_xh[(size_t)T * I * B];        // 16.8 MB (t,i,b) fp16
__device__ __align__(16) int2   g_ihcv[NNZ_IH];                 // (col, val-bits)
__device__ __align__(16) int2   g_hhcv[NNZ_HH];                 // (col, gamma-folded val)
__device__ int   g_ih_ptr[H + 1];
__device__ int   g_hh_ptr[H + 1];
__device__ int   g_ih_ofs[H];
__device__ int   g_hh_ofs[H];
__device__ float g_Sg[H];                                       // sum w_hh * gamma
__device__ float g_Sb[H];                                       // sum w_hh * beta
__device__ __align__(16) __half g_a16[(size_t)T * H * B];       // 64 MB act fp16 (t,r,b)
__device__ __align__(16) float  g_a32[(size_t)T * H * B];       // 128 MB act fp32 (t,r,b)
__device__ __align__(16) float  g_stats[(size_t)T * B * 2];     // (sum, sumsq) per (t,b)

// ---------------- preprocessing (exactly 4 kernels before the recurrence) ----------------

__global__ void k_init() {
    int idx = blockIdx.x * blockDim.x + threadIdx.x;
    int stride = gridDim.x * blockDim.x;
    for (int j = idx; j < H; j += stride) {
        g_ih_ofs[j] = 0; g_hh_ofs[j] = 0; g_Sg[j] = 0.f; g_Sb[j] = 0.f;
    }
    for (int j = idx; j < T * B * 2; j += stride) g_stats[j] = 0.f;
}

// histogram + x transpose fused (independent elementwise work)
__global__ void k_hist_tr(const int* __restrict__ ih_rows, const int* __restrict__ hh_rows,
                          const float* __restrict__ x) {
    size_t idx = (size_t)blockIdx.x * blockDim.x + threadIdx.x;
    size_t stride = (size_t)gridDim.x * blockDim.x;
    for (size_t e = idx; e < NNZ_HH; e += stride) {
        atomicAdd(&g_hh_ofs[hh_rows[e]], 1);
        if (e < NNZ_IH) atomicAdd(&g_ih_ofs[ih_rows[e]], 1);
    }
    const size_t total = (size_t)T * I * B;
    for (size_t j = idx; j < total; j += stride) {
        int b = (int)(j & (B - 1));
        int i = (int)((j >> 6) % I);
        int t = (int)((j >> 6) / I);
        g_xh[j] = __float2half(x[((size_t)b * T + t) * I + i]);
    }
}

// 1 block, 1024 threads: exclusive scan of both 4096-entry histograms
__global__ void k_scan() {
    __shared__ int s[H];
    __shared__ int aux[1024];
    int tid = threadIdx.x;
    for (int pass = 0; pass < 2; pass++) {
        int* cnt = pass ? g_hh_ofs : g_ih_ofs;
        int* ptr = pass ? g_hh_ptr : g_ih_ptr;
        for (int j = tid; j < H; j += 1024) s[j] = cnt[j];
        __syncthreads();
        int base = tid * 4;
        int a0 = s[base], a1 = s[base + 1], a2 = s[base + 2], a3 = s[base + 3];
        int tsum = a0 + a1 + a2 + a3;
        aux[tid] = tsum;
        __syncthreads();
        for (int off = 1; off < 1024; off <<= 1) {
            int v = (tid >= off) ? aux[tid - off] : 0;
            __syncthreads();
            aux[tid] += v;
            __syncthreads();
        }
        int excl = aux[tid] - tsum;
        int p0 = excl, p1 = excl + a0, p2 = excl + a0 + a1, p3 = excl + a0 + a1 + a2;
        ptr[base] = p0; ptr[base + 1] = p1; ptr[base + 2] = p2; ptr[base + 3] = p3;
        cnt[base] = p0; cnt[base + 1] = p1; cnt[base + 2] = p2; cnt[base + 3] = p3;
        if (tid == 1023) ptr[H] = aux[1023];
        __syncthreads();
    }
}

// scatter into CSR; fold gamma into hh vals; accumulate Sg/Sb row sums
__global__ void k_scatter(const int* __restrict__ ih_rows, const int* __restrict__ ih_cols,
                          const float* __restrict__ ih_vals,
                          const int* __restrict__ hh_rows, const int* __restrict__ hh_cols,
                          const float* __restrict__ hh_vals,
                          const float* __restrict__ gamma, const float* __restrict__ beta) {
    int idx = blockIdx.x * blockDim.x + threadIdx.x;
    int stride = gridDim.x * blockDim.x;
    for (int e = idx; e < NNZ_HH; e += stride) {
        int r = hh_rows[e], c = hh_cols[e];
        float v = hh_vals[e];
        float ga = __ldg(&gamma[c]);
        int p = atomicAdd(&g_hh_ofs[r], 1);
        g_hhcv[p] = make_int2(c, __float_as_int(v * ga));
        atomicAdd(&g_Sg[r], v * ga);
        atomicAdd(&g_Sb[r], v * __ldg(&beta[c]));
        if (e < NNZ_IH) {
            int r2 = ih_rows[e];
            int p2 = atomicAdd(&g_ih_ofs[r2], 1);
            g_ihcv[p2] = make_int2(ih_cols[e], __float_as_int(ih_vals[e]));
        }
    }
}

// ---------------- recurrence: one kernel per step ----------------
// warp per row; lane covers batches (2l, 2l+1) via half2. Weight chunks are loaded
// coalesced (1 LDG per 32 nnz per lane) and broadcast via shfl -> 32 independent
// gathers in flight (MLP 32). Next chunk prefetched across the inner loop.

__device__ __forceinline__ void gather32(const int2* __restrict__ cvbuf, int s, int e,
                                         const __half2* __restrict__ src, int lane,
                                         float2& acc) {
    int k0 = s + lane;
    int2 cv = (k0 < e) ? __ldg(&cvbuf[k0]) : make_int2(0, 0);
    for (int e0 = s; e0 < e; e0 += 32) {
        int kn = e0 + 32 + lane;
        int2 nxt = (kn < e) ? __ldg(&cvbuf[kn]) : make_int2(0, 0);
        #pragma unroll
        for (int k = 0; k < 32; k++) {
            int   cc = __shfl_sync(0xffffffffu, cv.x, k);
            float vv = __int_as_float(__shfl_sync(0xffffffffu, cv.y, k));
            float2 f = __half22float2(src[cc * 32 + lane]);
            acc.x = fmaf(vv, f.x, acc.x);
            acc.y = fmaf(vv, f.y, acc.y);
        }
        cv = nxt;
    }
}

__global__ void __launch_bounds__(256) k_spmm(const float* __restrict__ b_ih,
                                              const float* __restrict__ b_hh, int t) {
    __shared__ float s_a[8][64];
    int w    = threadIdx.x >> 5;
    int row  = blockIdx.x * 8 + w;
    int lane = threadIdx.x & 31;

    float mu0 = 0.f, iv0 = 0.f, mu1 = 0.f, iv1 = 0.f;
    if (t > 0) {
        float4 st = *reinterpret_cast<const float4*>(&g_stats[((size_t)(t - 1) * B + 2 * lane) * 2]);
        mu0 = st.x * (1.0f / (float)H);
        iv0 = rsqrtf(st.y * (1.0f / (float)H) - mu0 * mu0 + LN_EPS);
        mu1 = st.z * (1.0f / (float)H);
        iv1 = rsqrtf(st.w * (1.0f / (float)H) - mu1 * mu1 + LN_EPS);
    }

    // ---- ih pass ----
    float2 accx = make_float2(0.f, 0.f);
    {
        const __half2* xsrc = reinterpret_cast<const __half2*>(g_xh) + (size_t)t * I * 32;
        gather32(g_ihcv, __ldg(&g_ih_ptr[row]), __ldg(&g_ih_ptr[row + 1]), xsrc, lane, accx);
    }
    // ---- hh pass (raw acts of t-1; LN applied algebraically) ----
    float2 acch = make_float2(0.f, 0.f);
    if (t > 0) {
        const __half2* hsrc = reinterpret_cast<const __half2*>(g_a16) + (size_t)(t - 1) * H * 32;
        gather32(g_hhcv, __ldg(&g_hh_ptr[row]), __ldg(&g_hh_ptr[row + 1]), hsrc, lane, acch);
    }

    float cst = __ldg(&b_ih[row]) + __ldg(&b_hh[row]) + ((t > 0) ? __ldg(&g_Sb[row]) : 0.f);
    float sg  = (t > 0) ? __ldg(&g_Sg[row]) : 0.f;
    float a0 = tanhf(accx.x + cst + iv0 * acch.x - mu0 * iv0 * sg);
    float a1 = tanhf(accx.y + cst + iv1 * acch.y - mu1 * iv1 * sg);

    // archive acts (fp16 for next-step gather, fp32 for exact output)
    reinterpret_cast<__half2*>(g_a16)[((size_t)t * H + row) * 32 + lane] =
        __floats2half2_rn(a0, a1);
    reinterpret_cast<float2*>(g_a32)[((size_t)t * H + row) * 32 + lane] =
        make_float2(a0, a1);

    // block-tile LN stats -> global atomics (spread addresses)
    s_a[w][2 * lane] = a0;
    s_a[w][2 * lane + 1] = a1;
    __syncthreads();
    if (threadIdx.x < 64) {
        int b = threadIdx.x;
        float s = 0.f, q = 0.f;
        #pragma unroll
        for (int j = 0; j < 8; j++) { float v = s_a[j][b]; s += v; q += v * v; }
        atomicAdd(&g_stats[((size_t)t * B + b) * 2 + 0], s);
        atomicAdd(&g_stats[((size_t)t * B + b) * 2 + 1], q);
    }
}

// ---------------- batched output writer (off the recurrence path) ----------------
#define OUT_SMEM (256 * 65 * 4)

__global__ void __launch_bounds__(256) k_out(const float* __restrict__ gamma,
                                             const float* __restrict__ beta,
                                             float* __restrict__ out, int write_hlast) {
    extern __shared__ float s[];   // [256][65]
    int t = blockIdx.x >> 4;
    int r0 = (blockIdx.x & 15) * 256;
    int tid = threadIdx.x;

    const float2* a2 = reinterpret_cast<const float2*>(g_a32) + ((size_t)t * H + r0) * 32;
    for (int j = tid; j < 256 * 32; j += 256) {
        int r = j >> 5, l = j & 31;
        float2 v = __ldg(&a2[r * 32 + l]);
        s[r * 65 + 2 * l] = v.x;
        s[r * 65 + 2 * l + 1] = v.y;
    }
    __syncthreads();

    int w = tid >> 5, lane = tid & 31;
    float ga[8], be[8];
    #pragma unroll
    for (int j = 0; j < 8; j++) {
        int r = r0 + lane + 32 * j;
        ga[j] = __ldg(&gamma[r]); be[j] = __ldg(&beta[r]);
    }
    for (int bb = w; bb < 64; bb += 8) {
        float2 st = *reinterpret_cast<const float2*>(&g_stats[((size_t)t * B + bb) * 2]);
        float mu = st.x * (1.0f / (float)H);
        float iv = rsqrtf(st.y * (1.0f / (float)H) - mu * mu + LN_EPS);
        #pragma unroll
        for (int j = 0; j < 8; j++) {
            int rl = lane + 32 * j;
            float hv = (s[rl * 65 + bb] - mu) * iv * ga[j] + be[j];
            out[(size_t)bb * T * H + (size_t)t * H + r0 + rl] = hv;
            if (write_hlast && t == T - 1)
                out[(size_t)B * T * H + (size_t)bb * H + r0 + rl] = hv;
        }
    }
}

// ---------------- launch ----------------

extern "C" void kernel_launch(void* const* d_in, const int* in_sizes, int n_in,
                              void* d_out, int out_size) {
    const float* x       = (const float*)d_in[0];
    const int*   ih_rows = (const int*)  d_in[1];
    const int*   ih_cols = (const int*)  d_in[2];
    const float* ih_vals = (const float*)d_in[3];
    const int*   hh_rows = (const int*)  d_in[4];
    const int*   hh_cols = (const int*)  d_in[5];
    const float* hh_vals = (const float*)d_in[6];
    const float* b_ih    = (const float*)d_in[7];
    const float* b_hh    = (const float*)d_in[8];
    const float* gamma   = (const float*)d_in[9];
    const float* beta    = (const float*)d_in[10];
    float* out = (float*)d_out;

    cudaFuncSetAttribute(k_out, cudaFuncAttributeMaxDynamicSharedMemorySize, OUT_SMEM);

    // preprocessing: 4 kernels -> ncu (-s 5) captures spmm(t=1)
    k_init<<<128, 256>>>();
    k_hist_tr<<<2048, 256>>>(ih_rows, hh_rows, x);
    k_scan<<<1, 1024>>>();
    k_scatter<<<1024, 256>>>(ih_rows, ih_cols, ih_vals, hh_rows, hh_cols, hh_vals,
                             gamma, beta);

    // recurrence: only spmm kernels on the critical path
    for (int t = 0; t < T; t++)
        k_spmm<<<512, 256>>>(b_ih, b_hh, t);

    // batched LN + output writes
    int can_hlast = ((size_t)out_size >= (size_t)B * T * H + (size_t)B * H) ? 1 : 0;
    k_out<<<T * 16, 256, OUT_SMEM>>>(gamma, beta, out, can_hlast);
}